// round 8
// baseline (speedup 1.0000x reference)
#include <cuda_runtime.h>
#include <cuda_bf16.h>
#include <math.h>
#include <stdint.h>

// Problem constants
#define N_POS 4096
#define C_CH  512
#define D_K   64

// ---------------- device scratch (no allocations allowed) -------------------
__device__ float g_kx[D_K * N_POS];                    // [64][4096]
__device__ float g_qx[D_K * N_POS];                    // [64][4096]
__device__ float g_S[(size_t)N_POS * N_POS];           // [4096][4096] raw scores
__device__ __nv_bfloat16 g_Phi[(size_t)N_POS * N_POS]; // softmax probs hi
__device__ __nv_bfloat16 g_Plo[(size_t)N_POS * N_POS]; // softmax probs lo
__device__ __nv_bfloat16 g_Vhi[(size_t)C_CH * N_POS];  // vx hi  [c][j]
__device__ __nv_bfloat16 g_Vlo[(size_t)C_CH * N_POS];  // vx lo  [c][j]

// bf16 mma.sync (m16n8k16, fp32 accum) — portable Ampere-era path, no 'a' features
__device__ __forceinline__ void mma16816(float* c, const uint32_t* a,
                                         uint32_t b0, uint32_t b1) {
    asm volatile(
        "mma.sync.aligned.m16n8k16.row.col.f32.bf16.bf16.f32 "
        "{%0,%1,%2,%3}, {%4,%5,%6,%7}, {%8,%9}, {%0,%1,%2,%3};\n"
        : "+f"(c[0]), "+f"(c[1]), "+f"(c[2]), "+f"(c[3])
        : "r"(a[0]), "r"(a[1]), "r"(a[2]), "r"(a[3]), "r"(b0), "r"(b1));
}

// ----------------------------------------------------------------------------
// Kernel 1: projections  C[M,N] = W[M,512] @ x[512,4096]
// sel 0 -> g_kx fp32, 1 -> g_qx fp32, 2 -> g_Vhi/g_Vlo bf16 split
// ----------------------------------------------------------------------------
__global__ __launch_bounds__(256) void proj_gemm_kernel(
    const float* __restrict__ W, const float* __restrict__ x, int sel)
{
    __shared__ float a_sh[16][64];
    __shared__ float b_sh[16][64];

    const int t  = threadIdx.x;
    const int tx = t & 15;
    const int ty = t >> 4;
    const int n0 = blockIdx.x * 64;
    const int m0 = blockIdx.y * 64;

    float acc[4][4] = {};

    for (int k0 = 0; k0 < C_CH; k0 += 16) {
        {
            int m  = t >> 2;
            int kk = (t & 3) << 2;
            float4 av = *(const float4*)&W[(size_t)(m0 + m) * C_CH + k0 + kk];
            a_sh[kk + 0][m] = av.x; a_sh[kk + 1][m] = av.y;
            a_sh[kk + 2][m] = av.z; a_sh[kk + 3][m] = av.w;
        }
        {
            int kk = t >> 4;
            int n  = (t & 15) << 2;
            *(float4*)&b_sh[kk][n] = *(const float4*)&x[(size_t)(k0 + kk) * N_POS + n0 + n];
        }
        __syncthreads();
#pragma unroll
        for (int kk = 0; kk < 16; kk++) {
            float4 a4 = *(const float4*)&a_sh[kk][ty * 4];
            float4 b4 = *(const float4*)&b_sh[kk][tx * 4];
            float af[4] = {a4.x, a4.y, a4.z, a4.w};
            float bf[4] = {b4.x, b4.y, b4.z, b4.w};
#pragma unroll
            for (int u = 0; u < 4; u++)
#pragma unroll
                for (int v = 0; v < 4; v++)
                    acc[u][v] = fmaf(af[u], bf[v], acc[u][v]);
        }
        __syncthreads();
    }

    if (sel == 2) {
#pragma unroll
        for (int u = 0; u < 4; u++) {
            size_t base = (size_t)(m0 + ty * 4 + u) * N_POS + n0 + tx * 4;
            __nv_bfloat16 h[4], l[4];
#pragma unroll
            for (int v = 0; v < 4; v++) {
                h[v] = __float2bfloat16(acc[u][v]);
                l[v] = __float2bfloat16(acc[u][v] - __bfloat162float(h[v]));
            }
            __nv_bfloat162 h01; h01.x = h[0]; h01.y = h[1];
            __nv_bfloat162 h23; h23.x = h[2]; h23.y = h[3];
            __nv_bfloat162 l01; l01.x = l[0]; l01.y = l[1];
            __nv_bfloat162 l23; l23.x = l[2]; l23.y = l[3];
            *(__nv_bfloat162*)&g_Vhi[base + 0] = h01;
            *(__nv_bfloat162*)&g_Vhi[base + 2] = h23;
            *(__nv_bfloat162*)&g_Vlo[base + 0] = l01;
            *(__nv_bfloat162*)&g_Vlo[base + 2] = l23;
        }
    } else {
        float* C = (sel == 0) ? g_kx : g_qx;
#pragma unroll
        for (int u = 0; u < 4; u++) {
            float4 o = make_float4(acc[u][0], acc[u][1], acc[u][2], acc[u][3]);
            *(float4*)&C[(size_t)(m0 + ty * 4 + u) * N_POS + n0 + tx * 4] = o;
        }
    }
}

// ----------------------------------------------------------------------------
// Kernel 2: scores  S[i][j] = sum_d kx[d][i] * qx[d][j]  (fp32 SIMT, ~57us)
// ----------------------------------------------------------------------------
__global__ __launch_bounds__(256) void score_gemm_kernel()
{
    __shared__ float a_sh[64][64];
    __shared__ float b_sh[64][64];

    const int t  = threadIdx.x;
    const int tx = t & 15;
    const int ty = t >> 4;
    const int j0 = blockIdx.x * 64;
    const int i0 = blockIdx.y * 64;

#pragma unroll
    for (int r = 0; r < 16; r++) {
        int idx = t + r * 256;
        int d = idx >> 6;
        int c = idx & 63;
        a_sh[d][c] = g_kx[(size_t)d * N_POS + i0 + c];
        b_sh[d][c] = g_qx[(size_t)d * N_POS + j0 + c];
    }
    __syncthreads();

    float acc[4][4] = {};
#pragma unroll
    for (int d = 0; d < 64; d++) {
        float4 a4 = *(const float4*)&a_sh[d][ty * 4];
        float4 b4 = *(const float4*)&b_sh[d][tx * 4];
        float af[4] = {a4.x, a4.y, a4.z, a4.w};
        float bf[4] = {b4.x, b4.y, b4.z, b4.w};
#pragma unroll
        for (int u = 0; u < 4; u++)
#pragma unroll
            for (int v = 0; v < 4; v++)
                acc[u][v] = fmaf(af[u], bf[v], acc[u][v]);
    }

#pragma unroll
    for (int u = 0; u < 4; u++) {
        float4 o = make_float4(acc[u][0], acc[u][1], acc[u][2], acc[u][3]);
        *(float4*)&g_S[(size_t)(i0 + ty * 4 + u) * N_POS + j0 + tx * 4] = o;
    }
}

// ----------------------------------------------------------------------------
// Kernel 3: softmax rows of g_S -> split-bf16 probs (g_Phi + g_Plo)
// ----------------------------------------------------------------------------
__global__ __launch_bounds__(256) void softmax_kernel()
{
    const int warp = (blockIdx.x * blockDim.x + threadIdx.x) >> 5;
    const int lane = threadIdx.x & 31;
    if (warp >= N_POS) return;

    const float* row = g_S + (size_t)warp * N_POS;

    float m = -INFINITY;
#pragma unroll 4
    for (int j = lane * 4; j < N_POS; j += 128) {
        float4 v = *(const float4*)&row[j];
        m = fmaxf(m, fmaxf(fmaxf(v.x, v.y), fmaxf(v.z, v.w)));
    }
#pragma unroll
    for (int o = 16; o; o >>= 1) m = fmaxf(m, __shfl_xor_sync(0xffffffffu, m, o));

    float l = 0.f;
#pragma unroll 4
    for (int j = lane * 4; j < N_POS; j += 128) {
        float4 v = *(const float4*)&row[j];
        l += __expf(v.x - m) + __expf(v.y - m) + __expf(v.z - m) + __expf(v.w - m);
    }
#pragma unroll
    for (int o = 16; o; o >>= 1) l += __shfl_xor_sync(0xffffffffu, l, o);

    const float linv = 1.0f / l;
    __nv_bfloat16* hrow = g_Phi + (size_t)warp * N_POS;
    __nv_bfloat16* lrow = g_Plo + (size_t)warp * N_POS;

#pragma unroll 4
    for (int j = lane * 4; j < N_POS; j += 128) {
        float4 v = *(const float4*)&row[j];
        float p[4] = {__expf(v.x - m) * linv, __expf(v.y - m) * linv,
                      __expf(v.z - m) * linv, __expf(v.w - m) * linv};
        __nv_bfloat16 h[4], lo[4];
#pragma unroll
        for (int q = 0; q < 4; q++) {
            h[q]  = __float2bfloat16(p[q]);
            lo[q] = __float2bfloat16(p[q] - __bfloat162float(h[q]));
        }
        __nv_bfloat162 h01; h01.x = h[0];  h01.y = h[1];
        __nv_bfloat162 h23; h23.x = h[2];  h23.y = h[3];
        __nv_bfloat162 l01; l01.x = lo[0]; l01.y = lo[1];
        __nv_bfloat162 l23; l23.x = lo[2]; l23.y = lo[3];
        *(__nv_bfloat162*)&hrow[j + 0] = h01;
        *(__nv_bfloat162*)&hrow[j + 2] = h23;
        *(__nv_bfloat162*)&lrow[j + 0] = l01;
        *(__nv_bfloat162*)&lrow[j + 2] = l23;
    }
}

// ----------------------------------------------------------------------------
// Kernel 4: PV via mma.sync bf16 (HMMA).  out[i][c] = sum_j P[i][j] * V[c][j]
// CTA tile 128i x 128c; 8 warps in 4(m) x 2(n); warp tile 32 x 64.
// K-chunks of 32 j. SMEM tiles padded to 40 bf16/row -> conflict-free LDS.
// Split bf16: acc += Phi*Vhi + Phi*Vlo + Plo*Vhi.
// ----------------------------------------------------------------------------
#define KC 32
#define APAD 40

__global__ __launch_bounds__(256) void pv_mma_kernel(float* __restrict__ out)
{
    __shared__ __nv_bfloat16 Ah[128][APAD];
    __shared__ __nv_bfloat16 Al[128][APAD];
    __shared__ __nv_bfloat16 Bh[128][APAD];
    __shared__ __nv_bfloat16 Bl[128][APAD];

    const int t    = threadIdx.x;
    const int wid  = t >> 5;
    const int lane = t & 31;
    const int wm   = wid >> 1;          // 0..3
    const int wn   = wid & 1;           // 0..1
    const int g    = lane >> 2;         // 0..7
    const int tq   = lane & 3;          // 0..3
    const int c0   = blockIdx.x * 128;
    const int i0   = blockIdx.y * 128;

    // staging: thread -> (row, 16-bf16 half) of each 128xKC tile
    const int srow  = t >> 1;
    const int shalf = (t & 1) * 16;
    const __nv_bfloat16* pPh = g_Phi + (size_t)(i0 + srow) * N_POS + shalf;
    const __nv_bfloat16* pPl = g_Plo + (size_t)(i0 + srow) * N_POS + shalf;
    const __nv_bfloat16* pVh = g_Vhi + (size_t)(c0 + srow) * N_POS + shalf;
    const __nv_bfloat16* pVl = g_Vlo + (size_t)(c0 + srow) * N_POS + shalf;

    float acc[2][8][4] = {};

    // prefetch chunk 0
    uint4 rPh0 = *(const uint4*)(pPh + 0), rPh1 = *(const uint4*)(pPh + 8);
    uint4 rPl0 = *(const uint4*)(pPl + 0), rPl1 = *(const uint4*)(pPl + 8);
    uint4 rVh0 = *(const uint4*)(pVh + 0), rVh1 = *(const uint4*)(pVh + 8);
    uint4 rVl0 = *(const uint4*)(pVl + 0), rVl1 = *(const uint4*)(pVl + 8);

    for (int c = 0; c < N_POS / KC; c++) {
        __syncthreads();   // previous chunk's compute done
        *(uint4*)&Ah[srow][shalf + 0] = rPh0;  *(uint4*)&Ah[srow][shalf + 8] = rPh1;
        *(uint4*)&Al[srow][shalf + 0] = rPl0;  *(uint4*)&Al[srow][shalf + 8] = rPl1;
        *(uint4*)&Bh[srow][shalf + 0] = rVh0;  *(uint4*)&Bh[srow][shalf + 8] = rVh1;
        *(uint4*)&Bl[srow][shalf + 0] = rVl0;  *(uint4*)&Bl[srow][shalf + 8] = rVl1;
        __syncthreads();

        if (c + 1 < N_POS / KC) {       // prefetch next chunk (hides GMEM latency)
            int co = (c + 1) * KC;
            rPh0 = *(const uint4*)(pPh + co);  rPh1 = *(const uint4*)(pPh + co + 8);
            rPl0 = *(const uint4*)(pPl + co);  rPl1 = *(const uint4*)(pPl + co + 8);
            rVh0 = *(const uint4*)(pVh + co);  rVh1 = *(const uint4*)(pVh + co + 8);
            rVl0 = *(const uint4*)(pVl + co);  rVl1 = *(const uint4*)(pVl + co + 8);
        }

#pragma unroll
        for (int ks = 0; ks < 2; ks++) {
            const int kb = ks * 16;
            uint32_t ah[2][4], al[2][4];
#pragma unroll
            for (int mt = 0; mt < 2; mt++) {
                const int rb = wm * 32 + mt * 16;
                ah[mt][0] = *(const uint32_t*)&Ah[rb + g][kb + 2 * tq];
                ah[mt][1] = *(const uint32_t*)&Ah[rb + g + 8][kb + 2 * tq];
                ah[mt][2] = *(const uint32_t*)&Ah[rb + g][kb + 2 * tq + 8];
                ah[mt][3] = *(const uint32_t*)&Ah[rb + g + 8][kb + 2 * tq + 8];
                al[mt][0] = *(const uint32_t*)&Al[rb + g][kb + 2 * tq];
                al[mt][1] = *(const uint32_t*)&Al[rb + g + 8][kb + 2 * tq];
                al[mt][2] = *(const uint32_t*)&Al[rb + g][kb + 2 * tq + 8];
                al[mt][3] = *(const uint32_t*)&Al[rb + g + 8][kb + 2 * tq + 8];
            }
#pragma unroll
            for (int nt = 0; nt < 8; nt++) {
                const int cr = wn * 64 + nt * 8 + g;
                uint32_t bh0 = *(const uint32_t*)&Bh[cr][kb + 2 * tq];
                uint32_t bh1 = *(const uint32_t*)&Bh[cr][kb + 2 * tq + 8];
                uint32_t bl0 = *(const uint32_t*)&Bl[cr][kb + 2 * tq];
                uint32_t bl1 = *(const uint32_t*)&Bl[cr][kb + 2 * tq + 8];
#pragma unroll
                for (int mt = 0; mt < 2; mt++) {
                    mma16816(acc[mt][nt], ah[mt], bh0, bh1);
                    mma16816(acc[mt][nt], ah[mt], bl0, bl1);
                    mma16816(acc[mt][nt], al[mt], bh0, bh1);
                }
            }
        }
    }

    // epilogue: c frag -> rows (g, g+8), cols (2tq, 2tq+1)
#pragma unroll
    for (int mt = 0; mt < 2; mt++) {
#pragma unroll
        for (int nt = 0; nt < 8; nt++) {
            const int ia = i0 + wm * 32 + mt * 16 + g;
            const int cc = c0 + wn * 64 + nt * 8 + 2 * tq;
            float2 lo = make_float2(acc[mt][nt][0], acc[mt][nt][1]);
            float2 hi = make_float2(acc[mt][nt][2], acc[mt][nt][3]);
            *(float2*)&out[(size_t)ia * C_CH + cc] = lo;
            *(float2*)&out[(size_t)(ia + 8) * C_CH + cc] = hi;
        }
    }
}

// ----------------------------------------------------------------------------
// Launch
// ----------------------------------------------------------------------------
extern "C" void kernel_launch(void* const* d_in, const int* in_sizes, int n_in,
                              void* d_out, int out_size)
{
    const float* x  = (const float*)d_in[0];  // [512, 4096]
    const float* Wk = (const float*)d_in[1];  // [64, 512]
    const float* Wq = (const float*)d_in[2];  // [64, 512]
    const float* Wv = (const float*)d_in[3];  // [512, 512]
    float* out = (float*)d_out;               // [4096, 512]

    proj_gemm_kernel<<<dim3(64, 1), 256>>>(Wk, x, 0);
    proj_gemm_kernel<<<dim3(64, 1), 256>>>(Wq, x, 1);
    proj_gemm_kernel<<<dim3(64, 8), 256>>>(Wv, x, 2);

    score_gemm_kernel<<<dim3(64, 64), 256>>>();

    softmax_kernel<<<512, 256>>>();

    pv_mma_kernel<<<dim3(C_CH / 128, N_POS / 128), 256>>>(out);
}